// round 16
// baseline (speedup 1.0000x reference)
#include <cuda_runtime.h>
#include <cuda_bf16.h>
#include <cstdint>

#define THREADS 512
#define VT      128000
#define VS      32000
#define KSEL    256
#define MAXB    640
#define TILE_F4    1000          // 4000 floats = 16000 bytes per tile
#define TILE_BYTES 16000
#define NTILES     32
#define NSTG       3
#define GRID       592

__device__ int g_ctr = 0;        // rows handed out = GRID + g_ctr
__device__ int g_done = 0;

struct __align__(128) Smem {
    float4   buf[NSTG][TILE_F4];         // 48000 B triple buffer
    unsigned cand[2 * MAXB];             // 5120 B: tKey0 = cand, tIdx0 = cand+MAXB
    unsigned hist[256];                  // 1024 B
    unsigned long long mbar[NSTG];
    unsigned selKey[KSEL], selIdx[KSEL];
    int      s_bin; unsigned s_above;
    int      nCand, selCount, nNext, s_is64, s_next;
    unsigned s_maxkey, s_minkey;
    float    s_mean, s_std, s_denom;
};

__device__ __forceinline__ unsigned f2k(float x) {
    unsigned u = __float_as_uint(x);
    return (u & 0x80000000u) ? ~u : (u | 0x80000000u);
}
__device__ __forceinline__ float k2f(unsigned k) {
    unsigned u = (k & 0x80000000u) ? (k & 0x7fffffffu) : ~k;
    return __uint_as_float(u);
}
__device__ __forceinline__ unsigned s2u(const void* p) {
    unsigned a;
    asm("{ .reg .u64 t; cvta.to.shared.u64 t, %1; cvt.u32.u64 %0, t; }"
        : "=r"(a) : "l"(p));
    return a;
}
__device__ __forceinline__ void mbar_init(unsigned a, unsigned cnt) {
    asm volatile("mbarrier.init.shared.b64 [%0], %1;" :: "r"(a), "r"(cnt) : "memory");
}
__device__ __forceinline__ void mbar_expect(unsigned a, unsigned bytes) {
    asm volatile("mbarrier.arrive.expect_tx.shared.b64 _, [%0], %1;"
                 :: "r"(a), "r"(bytes) : "memory");
}
__device__ __forceinline__ void bulk_g2s(unsigned dst, const void* src,
                                         unsigned bytes, unsigned mbar) {
    asm volatile("cp.async.bulk.shared::cta.global.mbarrier::complete_tx::bytes "
                 "[%0], [%1], %2, [%3];"
                 :: "r"(dst), "l"(src), "r"(bytes), "r"(mbar) : "memory");
}
__device__ __forceinline__ void mbar_wait(unsigned a, unsigned parity) {
    unsigned done;
    asm volatile(
        "{\n\t.reg .pred p;\n\t"
        "mbarrier.try_wait.parity.acquire.cta.shared::cta.b64 p, [%1], %2;\n\t"
        "selp.b32 %0, 1, 0, p;\n\t}"
        : "=r"(done) : "r"(a), "r"(parity) : "memory");
    if (!done) {
        asm volatile(
            "{\n\t.reg .pred P1;\n\t"
            "WL%=:\n\t"
            "mbarrier.try_wait.parity.acquire.cta.shared::cta.b64 P1, [%0], %1, 0x989680;\n\t"
            "@P1 bra.uni WD%=;\n\t"
            "bra.uni WL%=;\n\t"
            "WD%=:\n\t}"
            :: "r"(a), "r"(parity) : "memory");
    }
}

extern __shared__ char smem_raw[];

__global__ void __launch_bounds__(THREADS)
vocab_project_kernel(const float* __restrict__ logits,
                     const void* __restrict__ mapping,
                     float* __restrict__ out,
                     int nrows) {
    Smem* sm = (Smem*)smem_raw;
    const int tid = threadIdx.x;
    unsigned* tKey0 = sm->cand;
    unsigned* tIdx0 = sm->cand + MAXB;

    unsigned mb[NSTG], bu[NSTG];
#pragma unroll
    for (int s = 0; s < NSTG; s++) {
        mb[s] = s2u(&sm->mbar[s]);
        bu[s] = s2u(&sm->buf[s][0]);
    }

    if (tid == 0) {
        const unsigned* m32 = (const unsigned*)mapping;
        int all0 = 1;
        for (int i = 1; i < 64; i += 2)
            if (m32[i] != 0u) { all0 = 0; break; }
        sm->s_is64 = all0;
#pragma unroll
        for (int s = 0; s < NSTG; s++) mbar_init(mb[s], 1);
    }
    __syncthreads();

    int row = blockIdx.x;                 // first row = blockIdx
    int stg = 0;                          // stage cursor (cycles continuously)
    unsigned ph = 0;                      // per-stage parity bits

    // prologue: prefetch tiles 0,1,2 of first row into stages 0,1,2
    if (row < nrows && tid == 0) {
        const char* rb = (const char*)(logits + (size_t)row * VT);
#pragma unroll
        for (int s = 0; s < NSTG; s++) {
            mbar_expect(mb[s], TILE_BYTES);
            bulk_g2s(bu[s], rb + (size_t)s * TILE_BYTES, TILE_BYTES, mb[s]);
        }
    }

    while (row < nrows) {
        const float* __restrict__ rowf = logits + (size_t)row * VT;
        float* __restrict__ orow = out + (size_t)row * VS;

        if (tid == 0) {
            sm->nCand = 0; sm->selCount = 0; sm->s_denom = 0.0f;
            sm->s_maxkey = 0u; sm->s_minkey = 0xFFFFFFFFu;
        }
        __syncthreads();

        // ---- stream row: 3-stage pipeline, 2 tiles always in flight ----
        const float thr0 = 2.70f;         // E[count] ~ 445 for N(0,1)
        for (int k = 0; k < NTILES; k++) {
            const int st = stg;
            mbar_wait(mb[st], (ph >> st) & 1u);
            ph ^= 1u << st;
            if (k == NTILES - 4 && tid == 0)
                sm->s_next = GRID + atomicAdd(&g_ctr, 1);
            const float4* tb = sm->buf[st];
            const unsigned base = (unsigned)k * (TILE_F4 * 4);
            for (int i = tid; i < TILE_F4; i += THREADS) {
                float4 v = tb[i];
                float m = fmaxf(fmaxf(v.x, v.y), fmaxf(v.z, v.w));
                if (m >= thr0) {
                    float a4[4] = {v.x, v.y, v.z, v.w};
#pragma unroll
                    for (int j = 0; j < 4; j++) {
                        if (a4[j] >= thr0) {
                            unsigned key = f2k(a4[j]);
                            int p = atomicAdd(&sm->nCand, 1);
                            if (p < MAXB) {
                                tKey0[p] = key;
                                tIdx0[p] = base + i * 4 + j;
                                atomicMax(&sm->s_maxkey, key);
                                atomicMin(&sm->s_minkey, key);
                            }
                        }
                    }
                }
            }
            __syncthreads();
            if (tid == 0) {
                const int nk = k + NSTG;         // next unissued tile of this row
                if (nk < NTILES) {
                    mbar_expect(mb[st], TILE_BYTES);
                    bulk_g2s(bu[st], (const char*)rowf + (size_t)nk * TILE_BYTES,
                             TILE_BYTES, mb[st]);
                } else {
                    const int nt = nk - NTILES;  // next row tile 0,1,2
                    const int nextrow = sm->s_next;
                    if (nextrow < nrows) {
                        const char* nb = (const char*)(logits + (size_t)nextrow * VT);
                        mbar_expect(mb[st], TILE_BYTES);
                        bulk_g2s(bu[st], nb + (size_t)nt * TILE_BYTES, TILE_BYTES, mb[st]);
                    }
                }
            }
            stg = (st + 1 == NSTG) ? 0 : st + 1;
        }
        __syncthreads();
        const int nextrow = sm->s_next;
        int nc = sm->nCand;
        const bool ok = (nc >= KSEL && nc <= MAXB);

        // ---- rare fallback: LDG rescan with sampled-stats threshold ----
        // (next-row tiles already in flight; buffers untouched here)
        if (!ok) {
            const float4* rp = (const float4*)rowf;
            float* fred  = (float*)tKey0;           // alias: stats before rescan
            float* fred2 = fred + THREADS;
            float thrVal;
            {
                float x = rowf[tid * (VT / THREADS)];
                fred[tid] = x;
                fred2[tid] = x * x;
                __syncthreads();
                for (int s = THREADS / 2; s > 0; s >>= 1) {
                    if (tid < s) {
                        fred[tid] += fred[tid + s];
                        fred2[tid] += fred2[tid + s];
                    }
                    __syncthreads();
                }
                if (tid == 0) {
                    float mean = fred[0] * (1.0f / THREADS);
                    float var  = fred2[0] * (1.0f / THREADS) - mean * mean;
                    sm->s_mean = mean;
                    sm->s_std  = sqrtf(fmaxf(var, 1e-12f));
                }
                __syncthreads();
                thrVal = sm->s_mean + 2.45f * sm->s_std;
                if (fabsf(thrVal - thr0) < 0.05f * sm->s_std)
                    thrVal += (nc < KSEL) ? -0.60f * sm->s_std : 0.35f * sm->s_std;
            }
            for (int attempt = 0; attempt < 10; attempt++) {
                if (tid == 0) { sm->nCand = 0; sm->s_maxkey = 0u; sm->s_minkey = 0xFFFFFFFFu; }
                __syncthreads();
                for (int i = tid; i < VT / 4; i += THREADS) {
                    float4 v = rp[i];
                    float m = fmaxf(fmaxf(v.x, v.y), fmaxf(v.z, v.w));
                    if (m >= thrVal) {
                        float a4[4] = {v.x, v.y, v.z, v.w};
#pragma unroll
                        for (int j = 0; j < 4; j++) {
                            if (a4[j] >= thrVal) {
                                unsigned key = f2k(a4[j]);
                                int p = atomicAdd(&sm->nCand, 1);
                                if (p < MAXB) {
                                    tKey0[p] = key;
                                    tIdx0[p] = (unsigned)(i * 4 + j);
                                    atomicMax(&sm->s_maxkey, key);
                                    atomicMin(&sm->s_minkey, key);
                                }
                            }
                        }
                    }
                }
                __syncthreads();
                nc = sm->nCand;
                if (nc >= KSEL && nc <= MAXB) break;
                if (nc < KSEL) thrVal -= 0.60f * sm->s_std + 1e-6f;
                else           thrVal += 0.35f * sm->s_std + 1e-6f;
                __syncthreads();
            }
        }

        // ---- zero own output row ----
        {
            float4 z = make_float4(0.f, 0.f, 0.f, 0.f);
            float4* op = (float4*)orow;
            for (int i = tid; i < VS / 4; i += THREADS) op[i] = z;
        }

        // ---- exact top-KSEL: in-place byte-radix (register-staged partition) ----
        unsigned* hist = sm->hist;
        int curN = nc < MAXB ? nc : MAXB;
        int need = KSEL;
        const unsigned keyxor = sm->s_minkey ^ sm->s_maxkey;
        int level = (keyxor == 0u) ? -1 : (3 - (__clz(keyxor) >> 3));
        __syncthreads();

        for (; level >= 0 && need > 0; level--) {
            if (curN == need) break;               // take all remaining
            if (tid < 256) hist[tid] = 0u;
            __syncthreads();
            const int sh = level * 8;
            unsigned myK[2], myI[2];
            int mycnt = 0;
            for (int p = tid; p < curN; p += THREADS) {
                unsigned key = tKey0[p];
                myK[mycnt] = key;
                myI[mycnt] = tIdx0[p];
                mycnt++;
                atomicAdd(&hist[(key >> sh) & 0xFFu], 1u);
            }
            __syncthreads();
            if (tid < 32) {
                unsigned local[8];
                unsigned part = 0;
#pragma unroll
                for (int j = 0; j < 8; j++) {
                    local[j] = hist[255 - (tid * 8 + j)];
                    part += local[j];
                }
                unsigned incl = part;
#pragma unroll
                for (int off = 1; off < 32; off <<= 1) {
                    unsigned v = __shfl_up_sync(0xffffffffu, incl, off);
                    if (tid >= off) incl += v;
                }
                unsigned before = incl - part;
                if (before < (unsigned)need && incl >= (unsigned)need) {
                    unsigned cum = before;
#pragma unroll
                    for (int j = 0; j < 8; j++) {
                        unsigned cj = local[j];
                        if (cum + cj >= (unsigned)need) {
                            sm->s_bin = 255 - (tid * 8 + j);
                            sm->s_above = cum;
                            break;
                        }
                        cum += cj;
                    }
                }
            }
            if (tid == 0) sm->nNext = 0;
            __syncthreads();
            const int c = sm->s_bin;
            const int G = (int)sm->s_above;
            for (int j = 0; j < mycnt; j++) {
                int byte = (int)((myK[j] >> sh) & 0xFFu);
                if (byte > c) {
                    int q = atomicAdd(&sm->selCount, 1);
                    sm->selKey[q] = myK[j]; sm->selIdx[q] = myI[j];
                } else if (byte == c) {
                    int q = atomicAdd(&sm->nNext, 1);
                    tKey0[q] = myK[j]; tIdx0[q] = myI[j];
                }
            }
            __syncthreads();
            need -= G;
            curN = sm->nNext;
            __syncthreads();
        }

        if (need > 0) {
            if (curN == need) {
                for (int p = tid; p < curN; p += THREADS) {
                    int q = atomicAdd(&sm->selCount, 1);
                    sm->selKey[q] = tKey0[p]; sm->selIdx[q] = tIdx0[p];
                }
            } else {
                // identical keys remain; take `need` smallest indices
                for (int p = tid; p < curN; p += THREADS) {
                    unsigned my = tIdx0[p];
                    int rank = 0;
                    for (int j = 0; j < curN; j++) rank += (tIdx0[j] < my);
                    if (rank < need) {
                        int q = atomicAdd(&sm->selCount, 1);
                        sm->selKey[q] = tKey0[p]; sm->selIdx[q] = my;
                    }
                }
            }
            __syncthreads();
        }

        const float vmax = k2f(sm->s_maxkey);

        // ---- weights + denominator ----
        float w = 0.0f;
        if (tid < KSEL) {
            w = exp2f((k2f(sm->selKey[tid]) - vmax) * 0.36067376022224085f);
            float ws = w;
#pragma unroll
            for (int off = 16; off > 0; off >>= 1)
                ws += __shfl_xor_sync(0xffffffffu, ws, off);
            if ((tid & 31) == 0) atomicAdd(&sm->s_denom, ws);
        }
        __syncthreads();
        const float inv = 1.0f / sm->s_denom;

        // ---- scatter ----
        if (tid < KSEL) {
            unsigned idx = sm->selIdx[tid];
            int sid;
            if (sm->s_is64) sid = (int)((const long long*)mapping)[idx];
            else            sid = ((const int*)mapping)[idx];
            atomicAdd(&orow[sid], w * inv);
        }
        __syncthreads();
        row = nextrow;
    }

    // ---- self-reset for graph replay ----
    __syncthreads();
    if (tid == 0) {
        __threadfence();
        int d = atomicAdd(&g_done, 1);
        if (d == (int)gridDim.x - 1) {
            g_ctr = 0;
            g_done = 0;
            __threadfence();
        }
    }
}

extern "C" void kernel_launch(void* const* d_in, const int* in_sizes, int n_in,
                              void* d_out, int out_size) {
    const float* logits  = (const float*)d_in[0];
    const void*  mapping = d_in[1];
    float* out = (float*)d_out;
    int rows = in_sizes[0] / VT;   // B*T = 2048
    int shbytes = (int)sizeof(Smem);
    cudaFuncSetAttribute(vocab_project_kernel,
                         cudaFuncAttributeMaxDynamicSharedMemorySize, shbytes);
    vocab_project_kernel<<<GRID, THREADS, shbytes>>>(logits, mapping, out, rows);
}

// round 17
// speedup vs baseline: 1.0450x; 1.0450x over previous
#include <cuda_runtime.h>
#include <cuda_bf16.h>
#include <cstdint>

#define THREADS 512
#define VT      128000
#define VS      32000
#define KSEL    256
#define MAXB    2048
#define TILE_F4    1000          // 4000 floats = 16000 bytes per tile
#define TILE_BYTES 16000
#define NTILES     32
#define ZCHUNK     (VS / 4 / NTILES)   // 250 float4 zero-stores per tile
#define GRID       592

__device__ int g_ctr = 0;        // rows handed out = GRID + g_ctr
__device__ int g_done = 0;

struct __align__(128) Smem {
    float4   buf[2][TILE_F4];            // 32000 B stream double buffer
    unsigned tKey0[MAXB], tIdx0[MAXB];   // 16384 B candidate store (in-place radix)
    unsigned long long mbar[2];
    unsigned selKey[KSEL], selIdx[KSEL];
    float    fred[THREADS], fred2[THREADS];
    int      s_bin; unsigned s_above;
    int      nCand, selCount, nNext, s_is64, s_next;
    unsigned s_maxkey, s_minkey;
    float    s_mean, s_std, s_denom;
};

__device__ __forceinline__ unsigned f2k(float x) {
    unsigned u = __float_as_uint(x);
    return (u & 0x80000000u) ? ~u : (u | 0x80000000u);
}
__device__ __forceinline__ float k2f(unsigned k) {
    unsigned u = (k & 0x80000000u) ? (k & 0x7fffffffu) : ~k;
    return __uint_as_float(u);
}
__device__ __forceinline__ unsigned s2u(const void* p) {
    unsigned a;
    asm("{ .reg .u64 t; cvta.to.shared.u64 t, %1; cvt.u32.u64 %0, t; }"
        : "=r"(a) : "l"(p));
    return a;
}
__device__ __forceinline__ void mbar_init(unsigned a, unsigned cnt) {
    asm volatile("mbarrier.init.shared.b64 [%0], %1;" :: "r"(a), "r"(cnt) : "memory");
}
__device__ __forceinline__ void mbar_expect(unsigned a, unsigned bytes) {
    asm volatile("mbarrier.arrive.expect_tx.shared.b64 _, [%0], %1;"
                 :: "r"(a), "r"(bytes) : "memory");
}
__device__ __forceinline__ void bulk_g2s(unsigned dst, const void* src,
                                         unsigned bytes, unsigned mbar) {
    asm volatile("cp.async.bulk.shared::cta.global.mbarrier::complete_tx::bytes "
                 "[%0], [%1], %2, [%3];"
                 :: "r"(dst), "l"(src), "r"(bytes), "r"(mbar) : "memory");
}
__device__ __forceinline__ void mbar_wait(unsigned a, unsigned parity) {
    unsigned done;
    asm volatile(
        "{\n\t.reg .pred p;\n\t"
        "mbarrier.try_wait.parity.acquire.cta.shared::cta.b64 p, [%1], %2;\n\t"
        "selp.b32 %0, 1, 0, p;\n\t}"
        : "=r"(done) : "r"(a), "r"(parity) : "memory");
    if (!done) {
        asm volatile(
            "{\n\t.reg .pred P1;\n\t"
            "WL%=:\n\t"
            "mbarrier.try_wait.parity.acquire.cta.shared::cta.b64 P1, [%0], %1, 0x989680;\n\t"
            "@P1 bra.uni WD%=;\n\t"
            "bra.uni WL%=;\n\t"
            "WD%=:\n\t}"
            :: "r"(a), "r"(parity) : "memory");
    }
}

extern __shared__ char smem_raw[];

__global__ void __launch_bounds__(THREADS)
vocab_project_kernel(const float* __restrict__ logits,
                     const void* __restrict__ mapping,
                     float* __restrict__ out,
                     int nrows) {
    Smem* sm = (Smem*)smem_raw;
    const int tid = threadIdx.x;

    const unsigned mb0 = s2u(&sm->mbar[0]);
    const unsigned mb1 = s2u(&sm->mbar[1]);
    const unsigned bu0 = s2u(&sm->buf[0][0]);
    const unsigned bu1 = s2u(&sm->buf[1][0]);

    if (tid == 0) {
        const unsigned* m32 = (const unsigned*)mapping;
        int all0 = 1;
        for (int i = 1; i < 64; i += 2)
            if (m32[i] != 0u) { all0 = 0; break; }
        sm->s_is64 = all0;
        mbar_init(mb0, 1);
        mbar_init(mb1, 1);
    }
    __syncthreads();

    int row = blockIdx.x;                 // first row = blockIdx
    int ph0 = 0, ph1 = 0;                 // persistent mbarrier phases

    // prologue: prefetch tiles 0,1 of first row
    if (row < nrows && tid == 0) {
        const char* rb = (const char*)(logits + (size_t)row * VT);
        mbar_expect(mb0, TILE_BYTES);
        bulk_g2s(bu0, rb, TILE_BYTES, mb0);
        mbar_expect(mb1, TILE_BYTES);
        bulk_g2s(bu1, rb + TILE_BYTES, TILE_BYTES, mb1);
    }

    while (row < nrows) {
        const float* __restrict__ rowf = logits + (size_t)row * VT;
        float* __restrict__ orow = out + (size_t)row * VS;

        if (tid == 0) {
            sm->nCand = 0; sm->selCount = 0; sm->s_denom = 0.0f;
            sm->s_maxkey = 0u; sm->s_minkey = 0xFFFFFFFFu;
        }
        __syncthreads();

        // ---- stream row through double buffer (tiles 0,1 already in flight) ----
        const float thr0 = 2.70f;         // E[count] ~ 445 for N(0,1)
        const float4 zv = make_float4(0.f, 0.f, 0.f, 0.f);
        float4* ozp = (float4*)orow;
        for (int k = 0; k < NTILES; k++) {
            const int b = k & 1;
            if (b == 0) { mbar_wait(mb0, ph0); ph0 ^= 1; }
            else        { mbar_wait(mb1, ph1); ph1 ^= 1; }
            // acquire next row id while processing tile NTILES-2
            if (k == NTILES - 2 && tid == 0)
                sm->s_next = GRID + atomicAdd(&g_ctr, 1);
            const float4* tb = sm->buf[b];
            const unsigned base = (unsigned)k * (TILE_F4 * 4);
            for (int i = tid; i < TILE_F4; i += THREADS) {
                float4 v = tb[i];
                float m = fmaxf(fmaxf(v.x, v.y), fmaxf(v.z, v.w));
                if (m >= thr0) {
                    float a4[4] = {v.x, v.y, v.z, v.w};
#pragma unroll
                    for (int j = 0; j < 4; j++) {
                        if (a4[j] >= thr0) {
                            unsigned key = f2k(a4[j]);
                            int p = atomicAdd(&sm->nCand, 1);
                            if (p < MAXB) {
                                sm->tKey0[p] = key;
                                sm->tIdx0[p] = base + i * 4 + j;
                                atomicMax(&sm->s_maxkey, key);
                                atomicMin(&sm->s_minkey, key);
                            }
                        }
                    }
                }
            }
            // interleaved output zeroing: 4 KB of this row per tile
            {
                const int zbase = k * ZCHUNK;
                for (int i = tid; i < ZCHUNK; i += THREADS)
                    ozp[zbase + i] = zv;
            }
            __syncthreads();
            if (tid == 0) {
                const int nk = k + 2;
                if (nk < NTILES) {
                    const unsigned mb = b ? mb1 : mb0;
                    const unsigned bu = b ? bu1 : bu0;
                    mbar_expect(mb, TILE_BYTES);
                    bulk_g2s(bu, (const char*)rowf + (size_t)nk * TILE_BYTES,
                             TILE_BYTES, mb);
                } else {
                    // buffer freed by this sync belongs to next row's tile nk-NTILES
                    const int nt = nk - NTILES;          // 0 or 1
                    const int nextrow = sm->s_next;
                    if (nextrow < nrows) {
                        const char* nb = (const char*)(logits + (size_t)nextrow * VT);
                        const unsigned mb = b ? mb1 : mb0;
                        const unsigned bu = b ? bu1 : bu0;
                        mbar_expect(mb, TILE_BYTES);
                        bulk_g2s(bu, nb + (size_t)nt * TILE_BYTES, TILE_BYTES, mb);
                    }
                }
            }
        }
        __syncthreads();
        const int nextrow = sm->s_next;
        int nc = sm->nCand;
        const bool ok = (nc >= KSEL && nc <= MAXB);

        // ---- rare fallback: LDG rescan with sampled-stats threshold ----
        // (next-row tiles already in flight in the buffers; untouched here)
        if (!ok) {
            const float4* rp = (const float4*)rowf;
            float thrVal;
            {
                float x = rowf[tid * (VT / THREADS)];
                sm->fred[tid] = x;
                sm->fred2[tid] = x * x;
                __syncthreads();
                for (int s = THREADS / 2; s > 0; s >>= 1) {
                    if (tid < s) {
                        sm->fred[tid] += sm->fred[tid + s];
                        sm->fred2[tid] += sm->fred2[tid + s];
                    }
                    __syncthreads();
                }
                if (tid == 0) {
                    float mean = sm->fred[0] * (1.0f / THREADS);
                    float var  = sm->fred2[0] * (1.0f / THREADS) - mean * mean;
                    sm->s_mean = mean;
                    sm->s_std  = sqrtf(fmaxf(var, 1e-12f));
                }
                __syncthreads();
                thrVal = sm->s_mean + 2.45f * sm->s_std;
                if (fabsf(thrVal - thr0) < 0.05f * sm->s_std)
                    thrVal += (nc < KSEL) ? -0.60f * sm->s_std : 0.35f * sm->s_std;
            }
            for (int attempt = 0; attempt < 10; attempt++) {
                if (tid == 0) { sm->nCand = 0; sm->s_maxkey = 0u; sm->s_minkey = 0xFFFFFFFFu; }
                __syncthreads();
                for (int i = tid; i < VT / 4; i += THREADS) {
                    float4 v = rp[i];
                    float m = fmaxf(fmaxf(v.x, v.y), fmaxf(v.z, v.w));
                    if (m >= thrVal) {
                        float a4[4] = {v.x, v.y, v.z, v.w};
#pragma unroll
                        for (int j = 0; j < 4; j++) {
                            if (a4[j] >= thrVal) {
                                unsigned key = f2k(a4[j]);
                                int p = atomicAdd(&sm->nCand, 1);
                                if (p < MAXB) {
                                    sm->tKey0[p] = key;
                                    sm->tIdx0[p] = (unsigned)(i * 4 + j);
                                    atomicMax(&sm->s_maxkey, key);
                                    atomicMin(&sm->s_minkey, key);
                                }
                            }
                        }
                    }
                }
                __syncthreads();
                nc = sm->nCand;
                if (nc >= KSEL && nc <= MAXB) break;
                if (nc < KSEL) thrVal -= 0.60f * sm->s_std + 1e-6f;
                else           thrVal += 0.35f * sm->s_std + 1e-6f;
                __syncthreads();
            }
        }

        // ---- exact top-KSEL: in-place byte-radix (register-staged partition) ----
        unsigned* hist = (unsigned*)sm->fred;      // 256 x 4B histogram
        int curN = nc < MAXB ? nc : MAXB;
        int need = KSEL;
        const unsigned keyxor = sm->s_minkey ^ sm->s_maxkey;
        int level = (keyxor == 0u) ? -1 : (3 - (__clz(keyxor) >> 3));
        __syncthreads();

        for (; level >= 0 && need > 0; level--) {
            if (curN == need) break;               // take all remaining
            if (tid < 256) hist[tid] = 0u;
            __syncthreads();
            const int sh = level * 8;
            unsigned myK[4], myI[4];
            int mycnt = 0;
            for (int p = tid; p < curN; p += THREADS) {
                unsigned key = sm->tKey0[p];
                myK[mycnt] = key;
                myI[mycnt] = sm->tIdx0[p];
                mycnt++;
                atomicAdd(&hist[(key >> sh) & 0xFFu], 1u);
            }
            __syncthreads();
            if (tid < 32) {
                unsigned local[8];
                unsigned part = 0;
#pragma unroll
                for (int j = 0; j < 8; j++) {
                    local[j] = hist[255 - (tid * 8 + j)];
                    part += local[j];
                }
                unsigned incl = part;
#pragma unroll
                for (int off = 1; off < 32; off <<= 1) {
                    unsigned v = __shfl_up_sync(0xffffffffu, incl, off);
                    if (tid >= off) incl += v;
                }
                unsigned before = incl - part;
                if (before < (unsigned)need && incl >= (unsigned)need) {
                    unsigned cum = before;
#pragma unroll
                    for (int j = 0; j < 8; j++) {
                        unsigned cj = local[j];
                        if (cum + cj >= (unsigned)need) {
                            sm->s_bin = 255 - (tid * 8 + j);
                            sm->s_above = cum;
                            break;
                        }
                        cum += cj;
                    }
                }
            }
            if (tid == 0) sm->nNext = 0;
            __syncthreads();
            const int c = sm->s_bin;
            const int G = (int)sm->s_above;
            for (int j = 0; j < mycnt; j++) {
                int byte = (int)((myK[j] >> sh) & 0xFFu);
                if (byte > c) {
                    int q = atomicAdd(&sm->selCount, 1);
                    sm->selKey[q] = myK[j]; sm->selIdx[q] = myI[j];
                } else if (byte == c) {
                    int q = atomicAdd(&sm->nNext, 1);
                    sm->tKey0[q] = myK[j]; sm->tIdx0[q] = myI[j];
                }
            }
            __syncthreads();
            need -= G;
            curN = sm->nNext;
            __syncthreads();
        }

        if (need > 0) {
            if (curN == need) {
                for (int p = tid; p < curN; p += THREADS) {
                    int q = atomicAdd(&sm->selCount, 1);
                    sm->selKey[q] = sm->tKey0[p]; sm->selIdx[q] = sm->tIdx0[p];
                }
            } else {
                // identical keys remain; take `need` smallest indices
                for (int p = tid; p < curN; p += THREADS) {
                    unsigned my = sm->tIdx0[p];
                    int rank = 0;
                    for (int j = 0; j < curN; j++) rank += (sm->tIdx0[j] < my);
                    if (rank < need) {
                        int q = atomicAdd(&sm->selCount, 1);
                        sm->selKey[q] = sm->tKey0[p]; sm->selIdx[q] = my;
                    }
                }
            }
            __syncthreads();
        }

        const float vmax = k2f(sm->s_maxkey);

        // ---- weights + denominator ----
        float w = 0.0f;
        if (tid < KSEL) {
            w = exp2f((k2f(sm->selKey[tid]) - vmax) * 0.36067376022224085f);
            float ws = w;
#pragma unroll
            for (int off = 16; off > 0; off >>= 1)
                ws += __shfl_xor_sync(0xffffffffu, ws, off);
            if ((tid & 31) == 0) atomicAdd(&sm->s_denom, ws);
        }
        __syncthreads();
        const float inv = 1.0f / sm->s_denom;

        // ---- scatter ----
        if (tid < KSEL) {
            unsigned idx = sm->selIdx[tid];
            int sid;
            if (sm->s_is64) sid = (int)((const long long*)mapping)[idx];
            else            sid = ((const int*)mapping)[idx];
            atomicAdd(&orow[sid], w * inv);
        }
        __syncthreads();
        row = nextrow;
    }

    // ---- self-reset for graph replay ----
    __syncthreads();
    if (tid == 0) {
        __threadfence();
        int d = atomicAdd(&g_done, 1);
        if (d == (int)gridDim.x - 1) {
            g_ctr = 0;
            g_done = 0;
            __threadfence();
        }
    }
}

extern "C" void kernel_launch(void* const* d_in, const int* in_sizes, int n_in,
                              void* d_out, int out_size) {
    const float* logits  = (const float*)d_in[0];
    const void*  mapping = d_in[1];
    float* out = (float*)d_out;
    int rows = in_sizes[0] / VT;   // B*T = 2048
    int shbytes = (int)sizeof(Smem);
    cudaFuncSetAttribute(vocab_project_kernel,
                         cudaFuncAttributeMaxDynamicSharedMemorySize, shbytes);
    vocab_project_kernel<<<GRID, THREADS, shbytes>>>(logits, mapping, out, rows);
}